// round 3
// baseline (speedup 1.0000x reference)
#include <cuda_runtime.h>
#include <cstdint>

#define EPSV 1e-5f
constexpr int BB = 32, CIN = 240, C1 = 24, HH = 56, WWD = 56, HW = 3136;
constexpr int OUP = 240;
constexpr int KSPLIT = 120;            // K-half size

// Scratch — __device__ globals per allocation rules. Raw partial sums (no BN).
__device__ float g_pa[BB * C1 * HW];   // conv1x1 partial, k in [0,120)
__device__ float g_pb[BB * C1 * HW];   // conv1x1 partial, k in [120,240)

using u64 = unsigned long long;

__device__ __forceinline__ u64 pk2(float lo, float hi) {
    u64 r; asm("mov.b64 %0, {%1,%2};" : "=l"(r) : "f"(lo), "f"(hi)); return r;
}
__device__ __forceinline__ float2 up2(u64 v) {
    float2 f; asm("mov.b64 {%0,%1}, %2;" : "=f"(f.x), "=f"(f.y) : "l"(v)); return f;
}
__device__ __forceinline__ u64 fma2(u64 a, u64 b, u64 c) {
    u64 d; asm("fma.rn.f32x2 %0, %1, %2, %3;" : "=l"(d) : "l"(a), "l"(b), "l"(c)); return d;
}
__device__ __forceinline__ u64 add2(u64 a, u64 b) {
    u64 d; asm("add.rn.f32x2 %0, %1, %2;" : "=l"(d) : "l"(a), "l"(b)); return d;
}

// ---------------------------------------------------------------------------
// Kernel A: 1x1 conv partial sums, split-K. blockIdx.y selects K-half.
// 1 pixel/thread, 12 channel-pair f32x2 accumulators, LDS.128 weight fetch.
// Grid (392, 2) x 256 = 200704 threads -> ~42 warps/SM resident.
// ---------------------------------------------------------------------------
__global__ __launch_bounds__(256, 4) void kA(
    const float* __restrict__ x, const float* __restrict__ w) {
    __shared__ ulonglong2 ws[KSPLIT * 6];   // [k][c4]: {w[4c4..4c4+3][k]} dup-paired
    int tid = threadIdx.x;
    int half = blockIdx.y;
    int kbase = half * KSPLIT;
    u64* wsf = reinterpret_cast<u64*>(ws);
    for (int i = tid; i < KSPLIT * 12; i += 256) {
        int k = i / 12, c2 = i % 12;
        wsf[i] = pk2(w[(2 * c2) * CIN + kbase + k],
                     w[(2 * c2 + 1) * CIN + kbase + k]);
    }
    __syncthreads();

    int p = blockIdx.x * 256 + tid;         // pixel id (exact: 392*256 = 100352)
    int b = p / HW;
    int s = p - b * HW;
    const float* xp = x + (size_t)b * CIN * HW + (size_t)kbase * HW + s;

    u64 acc[12];
#pragma unroll
    for (int c2 = 0; c2 < 12; c2++) acc[c2] = 0ull;

    for (int k0 = 0; k0 < KSPLIT; k0 += 8) {
        float xv[8];
#pragma unroll
        for (int j = 0; j < 8; j++)
            xv[j] = __ldg(xp + (size_t)(k0 + j) * HW);
#pragma unroll
        for (int j = 0; j < 8; j++) {
            u64 xx = pk2(xv[j], xv[j]);
            const ulonglong2* wk = ws + (k0 + j) * 6;
#pragma unroll
            for (int c4 = 0; c4 < 6; c4++) {
                ulonglong2 wv = wk[c4];
                acc[2 * c4]     = fma2(xx, wv.x, acc[2 * c4]);
                acc[2 * c4 + 1] = fma2(xx, wv.y, acc[2 * c4 + 1]);
            }
        }
    }
    float* op = (half == 0 ? g_pa : g_pb) + (size_t)b * C1 * HW + s;
#pragma unroll
    for (int c2 = 0; c2 < 12; c2++) {
        float2 f = up2(acc[c2]);
        op[(size_t)(2 * c2) * HW] = f.x;
        op[(size_t)(2 * c2 + 1) * HW] = f.y;
    }
}

// ---------------------------------------------------------------------------
// Fused kernel BC: one block per (b,c) plane (768 blocks, 256 threads).
// Stage 1: sum partials + BN1, then dw3x3 + BN2 -> shared tile (+ out[:, :24]).
// Stage 2: adder depthwise (9 filters) + BN3 + ReLU -> out[:, 24:240).
// Register-dieted: unroll 1 on q-loops, min 3 CTAs/SM.
// ---------------------------------------------------------------------------
__global__ __launch_bounds__(256, 3) void kBC(
    const float* __restrict__ g1, const float* __restrict__ b1,
    const float* __restrict__ m1, const float* __restrict__ v1,
    const float* __restrict__ wdw,
    const float* __restrict__ g2, const float* __restrict__ b2,
    const float* __restrict__ m2, const float* __restrict__ v2,
    const float* __restrict__ wadd,
    const float* __restrict__ g3, const float* __restrict__ b3,
    const float* __restrict__ m3, const float* __restrict__ v3,
    float* __restrict__ out) {
    int c = blockIdx.x % C1;
    int b = blockIdx.x / C1;
    __shared__ float tile[HW];            // 12544 B dw output plane
    __shared__ u64 negtap[81];
    __shared__ float sninv[9], sbias[9];
    int tid = threadIdx.x;
    if (tid < 81) {
        float tv = wadd[c * 81 + tid];
        negtap[tid] = pk2(-tv, -tv);
    }
    if (tid < 9) {
        int ch = c * 9 + tid;
        float iv = g3[ch] * rsqrtf(v3[ch] + EPSV);
        sninv[tid] = -iv;
        sbias[tid] = b3[ch] - m3[ch] * iv;
    }
    float wv[9];
#pragma unroll
    for (int t = 0; t < 9; t++) wv[t] = __ldg(wdw + c * 9 + t);
    float iv1 = g1[c] * rsqrtf(v1[c] + EPSV);
    float bi1 = b1[c] - m1[c] * iv1;
    float iv2 = g2[c] * rsqrtf(v2[c] + EPSV);
    float bi2 = b2[c] - m2[c] * iv2;
    size_t poff = ((size_t)b * C1 + c) * HW;
    const float* pa = g_pa + poff;
    const float* pb = g_pb + poff;
    float* outc = out + ((size_t)b * OUP + c) * HW;

    // Stage 1: bn1(pa+pb) -> dw3x3 -> bn2, 4 px per iteration
#pragma unroll 1
    for (int q = tid; q < 784; q += 256) {
        int h = q / 14;
        int w0 = (q % 14) * 4;
        float rb[3][6];
#pragma unroll
        for (int dy = 0; dy < 3; dy++) {
            int hh = h + dy - 1;
            bool hok = (hh >= 0) && (hh < HH);
#pragma unroll
            for (int jx = 0; jx < 6; jx++) {
                int ww = w0 + jx - 1;
                int idx = hh * WWD + ww;
                rb[dy][jx] = (hok && ww >= 0 && ww < WWD)
                               ? fmaf(pa[idx] + pb[idx], iv1, bi1) : 0.0f;
            }
        }
        float acc[4] = {0.f, 0.f, 0.f, 0.f};
#pragma unroll
        for (int dy = 0; dy < 3; dy++)
#pragma unroll
            for (int dx = 0; dx < 3; dx++) {
                float t = wv[dy * 3 + dx];
#pragma unroll
                for (int j = 0; j < 4; j++) acc[j] = fmaf(rb[dy][dx + j], t, acc[j]);
            }
        float4 o = make_float4(fmaf(acc[0], iv2, bi2), fmaf(acc[1], iv2, bi2),
                               fmaf(acc[2], iv2, bi2), fmaf(acc[3], iv2, bi2));
        *reinterpret_cast<float4*>(tile + h * WWD + w0) = o;
        *reinterpret_cast<float4*>(outc + h * WWD + w0) = o;
    }
    __syncthreads();

    // Stage 2: adder + BN3 + ReLU from shared tile
    float* outa = out + ((size_t)b * OUP + C1 + c * 9) * HW;
#pragma unroll 1
    for (int q = tid; q < 784; q += 256) {
        int h = q / 14;
        int w0 = (q % 14) * 4;
        u64 nA[9], nB[9];
#pragma unroll
        for (int dy = 0; dy < 3; dy++) {
            int hh = h + dy - 1;
            bool hok = (hh >= 0) && (hh < HH);
            float r0, r1, r2, r3, r4, r5;
            {
                int ww = w0 - 1;
                r0 = (hok && ww >= 0) ? tile[hh * WWD + ww] : 0.0f;
            }
#pragma unroll
            for (int jx = 1; jx < 5; jx++) {
                int ww = w0 + jx - 1;
                float v = hok ? tile[hh * WWD + ww] : 0.0f;
                if (jx == 1) r1 = v; else if (jx == 2) r2 = v;
                else if (jx == 3) r3 = v; else r4 = v;
            }
            {
                int ww = w0 + 4;
                r5 = (hok && ww < WWD) ? tile[hh * WWD + ww] : 0.0f;
            }
            nA[dy * 3 + 0] = pk2(r0, r1); nB[dy * 3 + 0] = pk2(r2, r3);
            nA[dy * 3 + 1] = pk2(r1, r2); nB[dy * 3 + 1] = pk2(r3, r4);
            nA[dy * 3 + 2] = pk2(r2, r3); nB[dy * 3 + 2] = pk2(r4, r5);
        }
        size_t obase = (size_t)h * WWD + w0;
#pragma unroll
        for (int r = 0; r < 9; r++) {
            u64 aA = 0ull, aB = 0ull;
#pragma unroll
            for (int t = 0; t < 9; t++) {
                u64 nt = negtap[r * 9 + t];
                u64 dA = add2(nA[t], nt) & 0x7FFFFFFF7FFFFFFFull;
                u64 dB = add2(nB[t], nt) & 0x7FFFFFFF7FFFFFFFull;
                aA = add2(aA, dA);
                aB = add2(aB, dB);
            }
            float2 fa = up2(aA), fb = up2(aB);
            float ni = sninv[r], bi = sbias[r];
            float4 o = make_float4(fmaxf(fmaf(fa.x, ni, bi), 0.f),
                                   fmaxf(fmaf(fa.y, ni, bi), 0.f),
                                   fmaxf(fmaf(fb.x, ni, bi), 0.f),
                                   fmaxf(fmaf(fb.y, ni, bi), 0.f));
            *reinterpret_cast<float4*>(outa + (size_t)r * HW + obase) = o;
        }
    }
}

extern "C" void kernel_launch(void* const* d_in, const int* in_sizes, int n_in,
                              void* d_out, int out_size) {
    const float* x   = (const float*)d_in[0];
    const float* wp  = (const float*)d_in[1];
    const float* g1  = (const float*)d_in[2];
    const float* b1  = (const float*)d_in[3];
    const float* m1  = (const float*)d_in[4];
    const float* v1  = (const float*)d_in[5];
    const float* wdw = (const float*)d_in[6];
    const float* g2  = (const float*)d_in[7];
    const float* b2  = (const float*)d_in[8];
    const float* m2  = (const float*)d_in[9];
    const float* v2  = (const float*)d_in[10];
    const float* wa  = (const float*)d_in[11];
    const float* g3  = (const float*)d_in[12];
    const float* b3  = (const float*)d_in[13];
    const float* m3  = (const float*)d_in[14];
    const float* v3  = (const float*)d_in[15];
    float* out = (float*)d_out;

    kA<<<dim3(392, 2), 256>>>(x, wp);
    kBC<<<BB * C1, 256>>>(g1, b1, m1, v1, wdw, g2, b2, m2, v2,
                          wa, g3, b3, m3, v3, out);
}

// round 4
// speedup vs baseline: 1.2282x; 1.2282x over previous
#include <cuda_runtime.h>
#include <cstdint>

#define EPSV 1e-5f
constexpr int BB = 32, CIN = 240, C1 = 24, HH = 56, WWD = 56, HW = 3136;
constexpr int OUP = 240;
constexpr int KSPLIT = 120;

// Scratch — __device__ globals per allocation rules.
__device__ float g_pa[BB * C1 * HW];   // conv1x1 raw partial, k in [0,120)
__device__ float g_pb[BB * C1 * HW];   // conv1x1 raw partial, k in [120,240)
__device__ float g_s2[BB * C1 * HW];   // after dw3x3 + bn2 (== x1)

using u64 = unsigned long long;

__device__ __forceinline__ u64 pk2(float lo, float hi) {
    u64 r; asm("mov.b64 %0, {%1,%2};" : "=l"(r) : "f"(lo), "f"(hi)); return r;
}
__device__ __forceinline__ float2 up2(u64 v) {
    float2 f; asm("mov.b64 {%0,%1}, %2;" : "=f"(f.x), "=f"(f.y) : "l"(v)); return f;
}
__device__ __forceinline__ u64 fma2(u64 a, u64 b, u64 c) {
    u64 d; asm("fma.rn.f32x2 %0, %1, %2, %3;" : "=l"(d) : "l"(a), "l"(b), "l"(c)); return d;
}
__device__ __forceinline__ u64 add2(u64 a, u64 b) {
    u64 d; asm("add.rn.f32x2 %0, %1, %2;" : "=l"(d) : "l"(a), "l"(b)); return d;
}

// ---------------------------------------------------------------------------
// Kernel A: 1x1 conv raw partial sums, split-K (blockIdx.y = K-half).
// 1 px/thread, 12 channel-pair f32x2 accumulators.
// Shared weights laid out [c2][k] so one LDS.128 serves TWO k-steps.
// 128-thread blocks, grid (784,2)=1568 -> fine-grained tail, ~32 warps/SM.
// ---------------------------------------------------------------------------
__global__ __launch_bounds__(128, 8) void kA(
    const float* __restrict__ x, const float* __restrict__ w) {
    __shared__ ulonglong2 ws2[12 * (KSPLIT / 2)];   // [c2][kpair], 11.25 KB
    int tid = threadIdx.x;
    int half = blockIdx.y;
    int kbase = half * KSPLIT;
    u64* wsf = reinterpret_cast<u64*>(ws2);
    for (int i = tid; i < 12 * KSPLIT; i += 128) {
        int c2 = i / KSPLIT, k = i % KSPLIT;
        wsf[i] = pk2(w[(2 * c2) * CIN + kbase + k],
                     w[(2 * c2 + 1) * CIN + kbase + k]);
    }
    __syncthreads();

    int p = blockIdx.x * 128 + tid;         // 784*128 = 100352 pixels exact
    int b = p / HW;
    int s = p - b * HW;
    const float* xp = x + (size_t)b * CIN * HW + (size_t)kbase * HW + s;

    u64 acc[12];
#pragma unroll
    for (int c2 = 0; c2 < 12; c2++) acc[c2] = 0ull;

    for (int k0 = 0; k0 < KSPLIT; k0 += 8) {
        float xv[8];
#pragma unroll
        for (int j = 0; j < 8; j++)
            xv[j] = __ldg(xp + (size_t)(k0 + j) * HW);
#pragma unroll
        for (int j = 0; j < 8; j += 2) {
            u64 xx0 = pk2(xv[j], xv[j]);
            u64 xx1 = pk2(xv[j + 1], xv[j + 1]);
            int kp = (k0 + j) >> 1;
#pragma unroll
            for (int c2 = 0; c2 < 12; c2++) {
                ulonglong2 wv = ws2[c2 * (KSPLIT / 2) + kp];
                acc[c2] = fma2(xx0, wv.x, acc[c2]);
                acc[c2] = fma2(xx1, wv.y, acc[c2]);
            }
        }
    }
    float* op = (half ? g_pb : g_pa) + (size_t)b * C1 * HW + s;
#pragma unroll
    for (int c2 = 0; c2 < 12; c2++) {
        float2 f = up2(acc[c2]);
        op[(size_t)(2 * c2) * HW] = f.x;
        op[(size_t)(2 * c2 + 1) * HW] = f.y;
    }
}

// ---------------------------------------------------------------------------
// Kernel B: merge partials + BN1, depthwise 3x3 + BN2. One q (4px) per thread.
// Flat grid 2352 x 256. Writes g_s2 (for kC, via L2) and out channels [0,24).
// ---------------------------------------------------------------------------
__global__ __launch_bounds__(256) void kB(
    const float* __restrict__ g1, const float* __restrict__ b1,
    const float* __restrict__ m1, const float* __restrict__ v1,
    const float* __restrict__ wdw,
    const float* __restrict__ g2, const float* __restrict__ b2,
    const float* __restrict__ m2, const float* __restrict__ v2,
    float* __restrict__ out) {
    int idx = blockIdx.x * 256 + threadIdx.x;   // 602112 = 32*24*784
    int q = idx % 784;
    int c = (idx / 784) % C1;
    int b = idx / (784 * C1);
    int h = q / 14;
    int w0 = (q % 14) * 4;
    float iv1 = g1[c] * rsqrtf(v1[c] + EPSV);
    float bi1 = b1[c] - m1[c] * iv1;
    size_t poff = ((size_t)b * C1 + c) * HW;
    const float* pa = g_pa + poff;
    const float* pb = g_pb + poff;

    float rb[3][6];
#pragma unroll
    for (int dy = 0; dy < 3; dy++) {
        int hh = h + dy - 1;
        bool hok = (hh >= 0) && (hh < HH);
#pragma unroll
        for (int jx = 0; jx < 6; jx++) {
            int ww = w0 + jx - 1;
            int id2 = hh * WWD + ww;
            rb[dy][jx] = (hok && ww >= 0 && ww < WWD)
                           ? fmaf(pa[id2] + pb[id2], iv1, bi1) : 0.0f;
        }
    }
    float wv[9];
#pragma unroll
    for (int t = 0; t < 9; t++) wv[t] = __ldg(wdw + c * 9 + t);
    float acc[4] = {0.f, 0.f, 0.f, 0.f};
#pragma unroll
    for (int dy = 0; dy < 3; dy++)
#pragma unroll
        for (int dx = 0; dx < 3; dx++) {
            float t = wv[dy * 3 + dx];
#pragma unroll
            for (int j = 0; j < 4; j++) acc[j] = fmaf(rb[dy][dx + j], t, acc[j]);
        }
    float iv2 = g2[c] * rsqrtf(v2[c] + EPSV);
    float bi2 = b2[c] - m2[c] * iv2;
    float4 o = make_float4(fmaf(acc[0], iv2, bi2), fmaf(acc[1], iv2, bi2),
                           fmaf(acc[2], iv2, bi2), fmaf(acc[3], iv2, bi2));
    size_t off = poff + h * WWD + w0;
    *reinterpret_cast<float4*>(g_s2 + off) = o;
    size_t ooff = ((size_t)b * OUP + c) * HW + h * WWD + w0;
    *reinterpret_cast<float4*>(out + ooff) = o;
}

// ---------------------------------------------------------------------------
// Kernel C: adder depthwise (24 -> 216) + BN3 + ReLU into out channels [24,240).
// One q (4px) per thread, grid (7, 24, 32) x 128. Reads g_s2 from L2.
// ---------------------------------------------------------------------------
__global__ __launch_bounds__(128) void kC(
    const float* __restrict__ wadd,
    const float* __restrict__ g3, const float* __restrict__ b3,
    const float* __restrict__ m3, const float* __restrict__ v3,
    float* __restrict__ out) {
    int c = blockIdx.y;
    int b = blockIdx.z;
    __shared__ u64 negtap[81];
    __shared__ float sninv[9], sbias[9];
    int tid = threadIdx.x;
    if (tid < 81) {
        float tv = wadd[c * 81 + tid];
        negtap[tid] = pk2(-tv, -tv);
    }
    if (tid < 9) {
        int ch = c * 9 + tid;
        float iv = g3[ch] * rsqrtf(v3[ch] + EPSV);
        sninv[tid] = -iv;
        sbias[tid] = b3[ch] - m3[ch] * iv;
    }
    __syncthreads();
    int q = blockIdx.x * 128 + tid;
    if (q >= 784) return;
    int h = q / 14;
    int w0 = (q % 14) * 4;
    const float* p = g_s2 + ((size_t)b * C1 + c) * HW;

    float rb[3][6];
#pragma unroll
    for (int dy = 0; dy < 3; dy++) {
        int hh = h + dy - 1;
        bool hok = (hh >= 0) && (hh < HH);
#pragma unroll
        for (int jx = 0; jx < 6; jx++) {
            int ww = w0 + jx - 1;
            rb[dy][jx] = (hok && ww >= 0 && ww < WWD) ? p[hh * WWD + ww] : 0.0f;
        }
    }
    u64 nA[9], nB[9];
#pragma unroll
    for (int dy = 0; dy < 3; dy++)
#pragma unroll
        for (int dx = 0; dx < 3; dx++) {
            nA[dy * 3 + dx] = pk2(rb[dy][dx],     rb[dy][dx + 1]);
            nB[dy * 3 + dx] = pk2(rb[dy][dx + 2], rb[dy][dx + 3]);
        }
    size_t obase = ((size_t)b * OUP + C1 + c * 9) * HW + h * WWD + w0;
#pragma unroll
    for (int r = 0; r < 9; r++) {
        u64 aA = 0ull, aB = 0ull;
#pragma unroll
        for (int t = 0; t < 9; t++) {
            u64 nt = negtap[r * 9 + t];
            u64 dA = add2(nA[t], nt) & 0x7FFFFFFF7FFFFFFFull;
            u64 dB = add2(nB[t], nt) & 0x7FFFFFFF7FFFFFFFull;
            aA = add2(aA, dA);
            aB = add2(aB, dB);
        }
        float2 fa = up2(aA), fb = up2(aB);
        float ni = sninv[r], bi = sbias[r];
        float4 o = make_float4(fmaxf(fmaf(fa.x, ni, bi), 0.f),
                               fmaxf(fmaf(fa.y, ni, bi), 0.f),
                               fmaxf(fmaf(fb.x, ni, bi), 0.f),
                               fmaxf(fmaf(fb.y, ni, bi), 0.f));
        *reinterpret_cast<float4*>(out + obase + (size_t)r * HW) = o;
    }
}

extern "C" void kernel_launch(void* const* d_in, const int* in_sizes, int n_in,
                              void* d_out, int out_size) {
    const float* x   = (const float*)d_in[0];
    const float* wp  = (const float*)d_in[1];
    const float* g1  = (const float*)d_in[2];
    const float* b1  = (const float*)d_in[3];
    const float* m1  = (const float*)d_in[4];
    const float* v1  = (const float*)d_in[5];
    const float* wdw = (const float*)d_in[6];
    const float* g2  = (const float*)d_in[7];
    const float* b2  = (const float*)d_in[8];
    const float* m2  = (const float*)d_in[9];
    const float* v2  = (const float*)d_in[10];
    const float* wa  = (const float*)d_in[11];
    const float* g3  = (const float*)d_in[12];
    const float* b3  = (const float*)d_in[13];
    const float* m3  = (const float*)d_in[14];
    const float* v3  = (const float*)d_in[15];
    float* out = (float*)d_out;

    kA<<<dim3(784, 2), 128>>>(x, wp);
    kB<<<2352, 256>>>(g1, b1, m1, v1, wdw, g2, b2, m2, v2, out);
    kC<<<dim3(7, 24, 32), 128>>>(wa, g3, b3, m3, v3, out);
}